// round 2
// baseline (speedup 1.0000x reference)
#include <cuda_runtime.h>
#include <math.h>

#define BATCH 2
#define SEQ   2048
#define CH    1024
#define NHEAD 16
#define HD    64
#define MROWS (BATCH*SEQ)   // 4096

// scratch (allocation is forbidden; device globals are the sanctioned path)
__device__ float g_q[MROWS*CH];
__device__ float g_k[MROWS*CH];
__device__ float g_v[MROWS*CH];
__device__ float g_att[MROWS*CH];

// ---------------------------------------------------------------------------
// C[M,N] = A[M,K] @ W[K,N] + bias[N]; M%128==0, N%128==0, K%8==0.
// Classic 128x128x8 tile, 256 threads, 8x8 per thread.
// ---------------------------------------------------------------------------
__global__ void __launch_bounds__(256, 2)
sgemm_bias(const float* __restrict__ A, const float* __restrict__ W,
           const float* __restrict__ bias, float* __restrict__ out,
           int K, int N)
{
    __shared__ float As[8][132];   // transposed A tile, padded
    __shared__ float Bs[8][128];

    const int tid  = threadIdx.x;
    const int row0 = blockIdx.y * 128;
    const int col0 = blockIdx.x * 128;

    const int a_row = tid >> 1;          // 0..127
    const int a_col = (tid & 1) << 2;    // 0 or 4
    const int b_row = tid >> 5;          // 0..7
    const int b_col = (tid & 31) << 2;   // 0..124

    const int ty = tid >> 4;             // 0..15 -> rows ty*8..+7
    const int tx = tid & 15;             // 0..15 -> cols tx*8..+7

    const float* Aptr = A + (size_t)(row0 + a_row) * K + a_col;
    const float* Wptr = W + (size_t)b_row * N + col0 + b_col;

    float bb[8];
#pragma unroll
    for (int j = 0; j < 8; j++) bb[j] = bias[col0 + tx * 8 + j];

    float acc[8][8];
#pragma unroll
    for (int i = 0; i < 8; i++)
#pragma unroll
        for (int j = 0; j < 8; j++) acc[i][j] = 0.f;

    for (int k0 = 0; k0 < K; k0 += 8) {
        float4 av = *(const float4*)(Aptr + k0);
        float4 bv = *(const float4*)(Wptr + (size_t)k0 * N);
        As[a_col + 0][a_row] = av.x;
        As[a_col + 1][a_row] = av.y;
        As[a_col + 2][a_row] = av.z;
        As[a_col + 3][a_row] = av.w;
        *(float4*)&Bs[b_row][b_col] = bv;
        __syncthreads();

#pragma unroll
        for (int k = 0; k < 8; k++) {
            float4 a0 = *(const float4*)&As[k][ty * 8];
            float4 a1 = *(const float4*)&As[k][ty * 8 + 4];
            float4 b0 = *(const float4*)&Bs[k][tx * 8];
            float4 b1 = *(const float4*)&Bs[k][tx * 8 + 4];
            float ar[8] = {a0.x, a0.y, a0.z, a0.w, a1.x, a1.y, a1.z, a1.w};
            float br[8] = {b0.x, b0.y, b0.z, b0.w, b1.x, b1.y, b1.z, b1.w};
#pragma unroll
            for (int i = 0; i < 8; i++)
#pragma unroll
                for (int j = 0; j < 8; j++)
                    acc[i][j] += ar[i] * br[j];
        }
        __syncthreads();
    }

#pragma unroll
    for (int i = 0; i < 8; i++) {
        int r = row0 + ty * 8 + i;
#pragma unroll
        for (int jq = 0; jq < 2; jq++) {
            int c = col0 + tx * 8 + jq * 4;
            float4 o;
            o.x = acc[i][jq * 4 + 0] + bb[jq * 4 + 0];
            o.y = acc[i][jq * 4 + 1] + bb[jq * 4 + 1];
            o.z = acc[i][jq * 4 + 2] + bb[jq * 4 + 2];
            o.w = acc[i][jq * 4 + 3] + bb[jq * 4 + 3];
            *(float4*)(out + (size_t)r * N + c) = o;
        }
    }
}

// ---------------------------------------------------------------------------
// Flash attention with swapped roles:
//   out[i] = sum_{j<=i} softmax_j( (k_i . q_j) / sqrt(D) ) * v_j
// One block = 64 output rows (i) of one (b, head). 256 threads, 4x4 micro-tiles.
// q,k,v layout: [B*T, C] row-major (head h occupies cols h*64..h*64+63).
// ---------------------------------------------------------------------------
#define SQ_STRIDE 65
#define SP_STRIDE 65

__global__ void __launch_bounds__(256)
attn_kernel(const float* __restrict__ q, const float* __restrict__ k,
            const float* __restrict__ v, float* __restrict__ att)
{
    extern __shared__ float sm[];
    float* sQ  = sm;                       // [64][65]  Qe = k rows (i-tile)
    float* sKP = sm + 64 * SQ_STRIDE;      // [64][65]  Ke = q rows (j-tile), reused as P
    float* sV  = sm + 2 * 64 * SQ_STRIDE;  // [64][64]  v rows (j-tile)

    const int i0  = blockIdx.x * 64;
    const int bh  = blockIdx.y;
    const int b   = bh >> 4;
    const int h   = bh & 15;
    const int tid = threadIdx.x;
    const int ty  = tid >> 4;   // 0..15 -> rows 4ty..4ty+3
    const int tx  = tid & 15;   // 0..15 -> cols 4tx..4tx+3

    const size_t base = (size_t)b * SEQ * CH + (size_t)h * HD;
    const float* qh = q + base;
    const float* kh = k + base;
    const float* vh = v + base;

    // load Qe (= K rows of the i-tile)
    for (int p = tid; p < 64 * 16; p += 256) {
        int r  = p >> 4;
        int c4 = (p & 15) << 2;
        float4 t = *(const float4*)(kh + (size_t)(i0 + r) * CH + c4);
        sQ[r * SQ_STRIDE + c4 + 0] = t.x;
        sQ[r * SQ_STRIDE + c4 + 1] = t.y;
        sQ[r * SQ_STRIDE + c4 + 2] = t.z;
        sQ[r * SQ_STRIDE + c4 + 3] = t.w;
    }

    float acc[4][4];
    float m_i[4], l_i[4];
#pragma unroll
    for (int r = 0; r < 4; r++) {
        m_i[r] = -INFINITY;
        l_i[r] = 0.f;
#pragma unroll
        for (int c = 0; c < 4; c++) acc[r][c] = 0.f;
    }

    const float scale = 0.125f;  // 1/sqrt(64)

    for (int j0 = 0; j0 <= i0; j0 += 64) {
        __syncthreads();  // previous P/V consumption done (also covers sQ load, iter 0)

        // load Ke (= q rows j-tile) and V (= v rows j-tile)
        for (int p = tid; p < 64 * 16; p += 256) {
            int r  = p >> 4;
            int c4 = (p & 15) << 2;
            float4 tq = *(const float4*)(qh + (size_t)(j0 + r) * CH + c4);
            sKP[r * SP_STRIDE + c4 + 0] = tq.x;
            sKP[r * SP_STRIDE + c4 + 1] = tq.y;
            sKP[r * SP_STRIDE + c4 + 2] = tq.z;
            sKP[r * SP_STRIDE + c4 + 3] = tq.w;
            float4 tv = *(const float4*)(vh + (size_t)(j0 + r) * CH + c4);
            *(float4*)&sV[r * 64 + c4] = tv;
        }
        __syncthreads();

        // S[r][c] = Qe[i0+4ty+r] . Ke[j0+4tx+c]
        float s[4][4] = {{0.f}};
#pragma unroll 4
        for (int d = 0; d < 64; d++) {
            float qv[4], kv[4];
#pragma unroll
            for (int r = 0; r < 4; r++) qv[r] = sQ[(4 * ty + r) * SQ_STRIDE + d];
#pragma unroll
            for (int c = 0; c < 4; c++) kv[c] = sKP[(4 * tx + c) * SP_STRIDE + d];
#pragma unroll
            for (int r = 0; r < 4; r++)
#pragma unroll
                for (int c = 0; c < 4; c++)
                    s[r][c] += qv[r] * kv[c];
        }

        // scale + causal mask (only diagonal tile can violate j<=i)
        if (j0 == i0) {
#pragma unroll
            for (int r = 0; r < 4; r++)
#pragma unroll
                for (int c = 0; c < 4; c++) {
                    if (4 * tx + c > 4 * ty + r) s[r][c] = -INFINITY;
                    else                         s[r][c] *= scale;
                }
        } else {
#pragma unroll
            for (int r = 0; r < 4; r++)
#pragma unroll
                for (int c = 0; c < 4; c++) s[r][c] *= scale;
        }

        // online softmax per row — registers + shuffles only (no smem writes yet)
#pragma unroll
        for (int r = 0; r < 4; r++) {
            float mt = fmaxf(fmaxf(s[r][0], s[r][1]), fmaxf(s[r][2], s[r][3]));
#pragma unroll
            for (int off = 1; off < 16; off <<= 1)
                mt = fmaxf(mt, __shfl_xor_sync(0xffffffffu, mt, off));
            float mnew  = fmaxf(m_i[r], mt);
            float alpha = __expf(m_i[r] - mnew);
            float psum  = 0.f;
#pragma unroll
            for (int c = 0; c < 4; c++) {
                float p = __expf(s[r][c] - mnew);
                s[r][c] = p;
                psum += p;
            }
#pragma unroll
            for (int off = 1; off < 16; off <<= 1)
                psum += __shfl_xor_sync(0xffffffffu, psum, off);
            l_i[r] = l_i[r] * alpha + psum;
            m_i[r] = mnew;
#pragma unroll
            for (int c = 0; c < 4; c++) acc[r][c] *= alpha;
        }

        // RACE FIX: all Ke reads must complete before sKP is overwritten with P
        __syncthreads();

#pragma unroll
        for (int r = 0; r < 4; r++)
#pragma unroll
            for (int c = 0; c < 4; c++)
                sKP[(4 * ty + r) * SP_STRIDE + 4 * tx + c] = s[r][c];
        __syncthreads();

        // acc += P @ V
#pragma unroll 4
        for (int j = 0; j < 64; j++) {
            float pv[4];
#pragma unroll
            for (int r = 0; r < 4; r++) pv[r] = sKP[(4 * ty + r) * SP_STRIDE + j];
            float4 vv = *(const float4*)&sV[j * 64 + 4 * tx];
            float vvv[4] = {vv.x, vv.y, vv.z, vv.w};
#pragma unroll
            for (int r = 0; r < 4; r++)
#pragma unroll
                for (int c = 0; c < 4; c++)
                    acc[r][c] += pv[r] * vvv[c];
        }
    }

    // epilogue: normalize and write to att in [B*T, C] layout
#pragma unroll
    for (int r = 0; r < 4; r++) {
        float inv = 1.f / l_i[r];
        float4 o;
        o.x = acc[r][0] * inv;
        o.y = acc[r][1] * inv;
        o.z = acc[r][2] * inv;
        o.w = acc[r][3] * inv;
        size_t row = (size_t)b * SEQ + i0 + 4 * ty + r;
        *(float4*)(att + row * CH + h * HD + 4 * tx) = o;
    }
}

// ---------------------------------------------------------------------------
extern "C" void kernel_launch(void* const* d_in, const int* in_sizes, int n_in,
                              void* d_out, int out_size)
{
    const float* x  = (const float*)d_in[0];
    const float* Wq = (const float*)d_in[1];
    const float* bq = (const float*)d_in[2];
    const float* Wk = (const float*)d_in[3];
    const float* bk = (const float*)d_in[4];
    const float* Wv = (const float*)d_in[5];
    const float* bv = (const float*)d_in[6];
    const float* Wp = (const float*)d_in[7];
    const float* bp = (const float*)d_in[8];
    // d_in[9] = mask: known causal tril, hardcoded in the attention kernel.
    float* out = (float*)d_out;

    float *q, *k, *v, *att;
    cudaGetSymbolAddress((void**)&q,   g_q);
    cudaGetSymbolAddress((void**)&k,   g_k);
    cudaGetSymbolAddress((void**)&v,   g_v);
    cudaGetSymbolAddress((void**)&att, g_att);

    dim3 gproj(CH / 128, MROWS / 128);  // (8, 32)
    sgemm_bias<<<gproj, 256>>>(x, Wq, bq, q, CH, CH);
    sgemm_bias<<<gproj, 256>>>(x, Wk, bk, k, CH, CH);
    sgemm_bias<<<gproj, 256>>>(x, Wv, bv, v, CH, CH);

    const int smem = (2 * 64 * SQ_STRIDE + 64 * 64) * (int)sizeof(float);  // 49664 B
    cudaFuncSetAttribute(attn_kernel, cudaFuncAttributeMaxDynamicSharedMemorySize, smem);
    attn_kernel<<<dim3(SEQ / 64, BATCH * NHEAD), 256, smem>>>(q, k, v, att);

    sgemm_bias<<<gproj, 256>>>(att, Wp, bp, out, CH, CH);
}

// round 4
// speedup vs baseline: 1.4575x; 1.4575x over previous
#include <cuda_runtime.h>
#include <cuda_bf16.h>
#include <math.h>
#include <stdint.h>

#define BATCH 2
#define SEQ   2048
#define CH    1024
#define NHEAD 16
#define HD    64
#define MROWS (BATCH*SEQ)   // 4096

// ---------------------------------------------------------------------------
// scratch (allocation is forbidden; device globals are the sanctioned path)
// ---------------------------------------------------------------------------
__device__ float g_q[MROWS*CH];
__device__ float g_k[MROWS*CH];
__device__ float g_v[MROWS*CH];
__device__ float g_att[MROWS*CH];
__device__ __nv_bfloat16 g_xhi[MROWS*CH];      // split of x (reused for att)
__device__ __nv_bfloat16 g_xlo[MROWS*CH];
__device__ __nv_bfloat16 g_wthi[4*CH*CH];      // W^T hi, 4 weights
__device__ __nv_bfloat16 g_wtlo[4*CH*CH];      // W^T lo

// ---------------------------------------------------------------------------
// fp32 -> bf16 hi/lo elementwise split (vectorized by 4)
// ---------------------------------------------------------------------------
__global__ void split_kernel(const float* __restrict__ x,
                             __nv_bfloat16* __restrict__ hi,
                             __nv_bfloat16* __restrict__ lo, int n4)
{
    int i = blockIdx.x * blockDim.x + threadIdx.x;
    if (i >= n4) return;
    float4 v = ((const float4*)x)[i];
    float f[4] = {v.x, v.y, v.z, v.w};
    __nv_bfloat16 h[4], l[4];
#pragma unroll
    for (int u = 0; u < 4; u++) {
        h[u] = __float2bfloat16(f[u]);
        l[u] = __float2bfloat16(f[u] - __bfloat162float(h[u]));
    }
    ((uint2*)hi)[i] = *(uint2*)h;
    ((uint2*)lo)[i] = *(uint2*)l;
}

// ---------------------------------------------------------------------------
// W [K,N] fp32 -> W^T [N,K] bf16 hi/lo   (32x32 tiles, block 32x8)
// ---------------------------------------------------------------------------
__global__ void transpose_split_kernel(const float* __restrict__ W,
                                       __nv_bfloat16* __restrict__ Thi,
                                       __nv_bfloat16* __restrict__ Tlo)
{
    __shared__ float t[32][33];
    const int kk = blockIdx.y * 32;
    const int nn = blockIdx.x * 32;
    const int tx = threadIdx.x, ty = threadIdx.y;
#pragma unroll
    for (int j = 0; j < 4; j++)
        t[ty + j * 8][tx] = W[(size_t)(kk + ty + j * 8) * CH + nn + tx];
    __syncthreads();
#pragma unroll
    for (int j = 0; j < 4; j++) {
        float v = t[tx][ty + j * 8];
        __nv_bfloat16 h = __float2bfloat16(v);
        __nv_bfloat16 l = __float2bfloat16(v - __bfloat162float(h));
        size_t o = (size_t)(nn + ty + j * 8) * CH + kk + tx;
        Thi[o] = h;
        Tlo[o] = l;
    }
}

// ---------------------------------------------------------------------------
// mma.sync m16n8k16 bf16 (f32 accum) — base-ISA tensor path (HMMA in SASS)
// ---------------------------------------------------------------------------
__device__ __forceinline__ void mma16816(float c[4],
                                         uint32_t a0, uint32_t a1,
                                         uint32_t a2, uint32_t a3,
                                         uint32_t b0, uint32_t b1)
{
    asm volatile(
        "mma.sync.aligned.m16n8k16.row.col.f32.bf16.bf16.f32 "
        "{%0,%1,%2,%3}, {%4,%5,%6,%7}, {%8,%9}, {%0,%1,%2,%3};"
        : "+f"(c[0]), "+f"(c[1]), "+f"(c[2]), "+f"(c[3])
        : "r"(a0), "r"(a1), "r"(a2), "r"(a3), "r"(b0), "r"(b1));
}

// ---------------------------------------------------------------------------
// out[M,N] = (Ahi+Alo)[M,K] @ (Bhi+Blo)[N,K]^T + bias  (bf16x3 on HMMA)
// CTA tile 128x128, 8 warps (2x4), warp tile 64x32, K-chunk 64.
// ---------------------------------------------------------------------------
#define PITCH 72   // bf16 elems per smem row (64 data + 8 pad) -> conflict-free

__global__ void __launch_bounds__(256, 2)
gemm_mma_bf16x3(const __nv_bfloat16* __restrict__ Ahi,
                const __nv_bfloat16* __restrict__ Alo,
                const __nv_bfloat16* __restrict__ Bhi,   // [N,K] = W^T
                const __nv_bfloat16* __restrict__ Blo,
                const float* __restrict__ bias,
                float* __restrict__ out, int K, int N)
{
    extern __shared__ __nv_bfloat16 sm[];
    __nv_bfloat16* sAh = sm;                   // [128][PITCH]
    __nv_bfloat16* sAl = sm + 128 * PITCH;
    __nv_bfloat16* sBh = sm + 2 * 128 * PITCH;
    __nv_bfloat16* sBl = sm + 3 * 128 * PITCH;

    const int tid  = threadIdx.x;
    const int warp = tid >> 5;
    const int lane = tid & 31;
    const int grp  = lane >> 2;       // 0..7
    const int tig  = lane & 3;        // 0..3
    const int wm   = warp >> 2;       // 0..1
    const int wn   = warp & 3;        // 0..3

    const int m0 = blockIdx.y * 128;
    const int n0 = blockIdx.x * 128;

    float c[4][4][4];                 // [mt][nt][frag]
#pragma unroll
    for (int mt = 0; mt < 4; mt++)
#pragma unroll
        for (int nt = 0; nt < 4; nt++)
#pragma unroll
            for (int f = 0; f < 4; f++) c[mt][nt][f] = 0.f;

    const int row = tid >> 3;         // gmem->smem: 0..31 (x4 iters -> 128)
    const int cg  = tid & 7;          // 16B group within 128B row

    for (int k0 = 0; k0 < K; k0 += 64) {
        __syncthreads();
#pragma unroll
        for (int i = 0; i < 4; i++) {
            int r = row + i * 32;
            size_t ga = (size_t)(m0 + r) * K + k0 + cg * 8;
            size_t gb = (size_t)(n0 + r) * K + k0 + cg * 8;
            int so = r * PITCH + cg * 8;
            *(uint4*)&sAh[so] = *(const uint4*)(Ahi + ga);
            *(uint4*)&sAl[so] = *(const uint4*)(Alo + ga);
            *(uint4*)&sBh[so] = *(const uint4*)(Bhi + gb);
            *(uint4*)&sBl[so] = *(const uint4*)(Blo + gb);
        }
        __syncthreads();

#pragma unroll
        for (int ks = 0; ks < 4; ks++) {
            const int kof = ks * 16 + 2 * tig;
            // B fragments for 4 n-tiles (hi+lo)
            uint32_t bh[4][2], bl[4][2];
#pragma unroll
            for (int nt = 0; nt < 4; nt++) {
                int nrow = wn * 32 + nt * 8 + grp;
                bh[nt][0] = *(const uint32_t*)&sBh[nrow * PITCH + kof];
                bh[nt][1] = *(const uint32_t*)&sBh[nrow * PITCH + kof + 8];
                bl[nt][0] = *(const uint32_t*)&sBl[nrow * PITCH + kof];
                bl[nt][1] = *(const uint32_t*)&sBl[nrow * PITCH + kof + 8];
            }
#pragma unroll
            for (int mt = 0; mt < 4; mt++) {
                int mrow = wm * 64 + mt * 16 + grp;
                uint32_t ah0 = *(const uint32_t*)&sAh[mrow * PITCH + kof];
                uint32_t ah1 = *(const uint32_t*)&sAh[(mrow + 8) * PITCH + kof];
                uint32_t ah2 = *(const uint32_t*)&sAh[mrow * PITCH + kof + 8];
                uint32_t ah3 = *(const uint32_t*)&sAh[(mrow + 8) * PITCH + kof + 8];
                uint32_t al0 = *(const uint32_t*)&sAl[mrow * PITCH + kof];
                uint32_t al1 = *(const uint32_t*)&sAl[(mrow + 8) * PITCH + kof];
                uint32_t al2 = *(const uint32_t*)&sAl[mrow * PITCH + kof + 8];
                uint32_t al3 = *(const uint32_t*)&sAl[(mrow + 8) * PITCH + kof + 8];
#pragma unroll
                for (int nt = 0; nt < 4; nt++) {
                    mma16816(c[mt][nt], ah0, ah1, ah2, ah3, bh[nt][0], bh[nt][1]);
                    mma16816(c[mt][nt], ah0, ah1, ah2, ah3, bl[nt][0], bl[nt][1]);
                    mma16816(c[mt][nt], al0, al1, al2, al3, bh[nt][0], bh[nt][1]);
                }
            }
        }
    }

    // epilogue: C layout c0=C[grp][2t] c1=C[grp][2t+1] c2=C[grp+8][2t] c3=[grp+8][2t+1]
#pragma unroll
    for (int mt = 0; mt < 4; mt++) {
        int r0 = m0 + wm * 64 + mt * 16 + grp;
#pragma unroll
        for (int nt = 0; nt < 4; nt++) {
            int col = n0 + wn * 32 + nt * 8 + 2 * tig;
            float2 bv = *(const float2*)(bias + col);
            float2 o0 = {c[mt][nt][0] + bv.x, c[mt][nt][1] + bv.y};
            float2 o1 = {c[mt][nt][2] + bv.x, c[mt][nt][3] + bv.y};
            *(float2*)(out + (size_t)r0 * N + col) = o0;
            *(float2*)(out + (size_t)(r0 + 8) * N + col) = o1;
        }
    }
}

// ---------------------------------------------------------------------------
// Flash attention with swapped roles (unchanged, verified correct):
//   out[i] = sum_{j<=i} softmax_j( (k_i . q_j) / sqrt(D) ) * v_j
// ---------------------------------------------------------------------------
#define SQ_STRIDE 65
#define SP_STRIDE 65

__global__ void __launch_bounds__(256)
attn_kernel(const float* __restrict__ q, const float* __restrict__ k,
            const float* __restrict__ v, float* __restrict__ att)
{
    extern __shared__ float smf[];
    float* sQ  = smf;
    float* sKP = smf + 64 * SQ_STRIDE;
    float* sV  = smf + 2 * 64 * SQ_STRIDE;

    const int i0  = blockIdx.x * 64;
    const int bh  = blockIdx.y;
    const int b   = bh >> 4;
    const int h   = bh & 15;
    const int tid = threadIdx.x;
    const int ty  = tid >> 4;
    const int tx  = tid & 15;

    const size_t base = (size_t)b * SEQ * CH + (size_t)h * HD;
    const float* qh = q + base;
    const float* kh = k + base;
    const float* vh = v + base;

    for (int p = tid; p < 64 * 16; p += 256) {
        int r  = p >> 4;
        int c4 = (p & 15) << 2;
        float4 t = *(const float4*)(kh + (size_t)(i0 + r) * CH + c4);
        sQ[r * SQ_STRIDE + c4 + 0] = t.x;
        sQ[r * SQ_STRIDE + c4 + 1] = t.y;
        sQ[r * SQ_STRIDE + c4 + 2] = t.z;
        sQ[r * SQ_STRIDE + c4 + 3] = t.w;
    }

    float acc[4][4];
    float m_i[4], l_i[4];
#pragma unroll
    for (int r = 0; r < 4; r++) {
        m_i[r] = -INFINITY;
        l_i[r] = 0.f;
#pragma unroll
        for (int c = 0; c < 4; c++) acc[r][c] = 0.f;
    }

    const float scale = 0.125f;

    for (int j0 = 0; j0 <= i0; j0 += 64) {
        __syncthreads();

        for (int p = tid; p < 64 * 16; p += 256) {
            int r  = p >> 4;
            int c4 = (p & 15) << 2;
            float4 tq = *(const float4*)(qh + (size_t)(j0 + r) * CH + c4);
            sKP[r * SP_STRIDE + c4 + 0] = tq.x;
            sKP[r * SP_STRIDE + c4 + 1] = tq.y;
            sKP[r * SP_STRIDE + c4 + 2] = tq.z;
            sKP[r * SP_STRIDE + c4 + 3] = tq.w;
            float4 tv = *(const float4*)(vh + (size_t)(j0 + r) * CH + c4);
            *(float4*)&sV[r * 64 + c4] = tv;
        }
        __syncthreads();

        float s[4][4] = {{0.f}};
#pragma unroll 4
        for (int d = 0; d < 64; d++) {
            float qv[4], kv[4];
#pragma unroll
            for (int r = 0; r < 4; r++) qv[r] = sQ[(4 * ty + r) * SQ_STRIDE + d];
#pragma unroll
            for (int c = 0; c < 4; c++) kv[c] = sKP[(4 * tx + c) * SP_STRIDE + d];
#pragma unroll
            for (int r = 0; r < 4; r++)
#pragma unroll
                for (int c = 0; c < 4; c++)
                    s[r][c] += qv[r] * kv[c];
        }

        if (j0 == i0) {
#pragma unroll
            for (int r = 0; r < 4; r++)
#pragma unroll
                for (int c = 0; c < 4; c++) {
                    if (4 * tx + c > 4 * ty + r) s[r][c] = -INFINITY;
                    else                         s[r][c] *= scale;
                }
        } else {
#pragma unroll
            for (int r = 0; r < 4; r++)
#pragma unroll
                for (int c = 0; c < 4; c++) s[r][c] *= scale;
        }

#pragma unroll
        for (int r = 0; r < 4; r++) {
            float mt = fmaxf(fmaxf(s[r][0], s[r][1]), fmaxf(s[r][2], s[r][3]));
#pragma unroll
            for (int off = 1; off < 16; off <<= 1)
                mt = fmaxf(mt, __shfl_xor_sync(0xffffffffu, mt, off));
            float mnew  = fmaxf(m_i[r], mt);
            float alpha = __expf(m_i[r] - mnew);
            float psum  = 0.f;
#pragma unroll
            for (int c = 0; c < 4; c++) {
                float p = __expf(s[r][c] - mnew);
                s[r][c] = p;
                psum += p;
            }
#pragma unroll
            for (int off = 1; off < 16; off <<= 1)
                psum += __shfl_xor_sync(0xffffffffu, psum, off);
            l_i[r] = l_i[r] * alpha + psum;
            m_i[r] = mnew;
#pragma unroll
            for (int c = 0; c < 4; c++) acc[r][c] *= alpha;
        }

        __syncthreads();   // all Ke reads complete before P overwrites sKP

#pragma unroll
        for (int r = 0; r < 4; r++)
#pragma unroll
            for (int c = 0; c < 4; c++)
                sKP[(4 * ty + r) * SP_STRIDE + 4 * tx + c] = s[r][c];
        __syncthreads();

#pragma unroll 4
        for (int j = 0; j < 64; j++) {
            float pv[4];
#pragma unroll
            for (int r = 0; r < 4; r++) pv[r] = sKP[(4 * ty + r) * SP_STRIDE + j];
            float4 vv = *(const float4*)&sV[j * 64 + 4 * tx];
            float vvv[4] = {vv.x, vv.y, vv.z, vv.w};
#pragma unroll
            for (int r = 0; r < 4; r++)
#pragma unroll
                for (int c = 0; c < 4; c++)
                    acc[r][c] += pv[r] * vvv[c];
        }
    }

#pragma unroll
    for (int r = 0; r < 4; r++) {
        float inv = 1.f / l_i[r];
        float4 o;
        o.x = acc[r][0] * inv;
        o.y = acc[r][1] * inv;
        o.z = acc[r][2] * inv;
        o.w = acc[r][3] * inv;
        size_t row = (size_t)b * SEQ + i0 + 4 * ty + r;
        *(float4*)(att + row * CH + h * HD + 4 * tx) = o;
    }
}

// ---------------------------------------------------------------------------
extern "C" void kernel_launch(void* const* d_in, const int* in_sizes, int n_in,
                              void* d_out, int out_size)
{
    const float* x  = (const float*)d_in[0];
    const float* Wq = (const float*)d_in[1];
    const float* bq = (const float*)d_in[2];
    const float* Wk = (const float*)d_in[3];
    const float* bk = (const float*)d_in[4];
    const float* Wv = (const float*)d_in[5];
    const float* bv = (const float*)d_in[6];
    const float* Wp = (const float*)d_in[7];
    const float* bp = (const float*)d_in[8];
    float* out = (float*)d_out;

    float *q, *k, *v, *att;
    __nv_bfloat16 *xhi, *xlo, *wthi, *wtlo;
    cudaGetSymbolAddress((void**)&q,    g_q);
    cudaGetSymbolAddress((void**)&k,    g_k);
    cudaGetSymbolAddress((void**)&v,    g_v);
    cudaGetSymbolAddress((void**)&att,  g_att);
    cudaGetSymbolAddress((void**)&xhi,  g_xhi);
    cudaGetSymbolAddress((void**)&xlo,  g_xlo);
    cudaGetSymbolAddress((void**)&wthi, g_wthi);
    cudaGetSymbolAddress((void**)&wtlo, g_wtlo);

    const int gemm_smem = 4 * 128 * PITCH * (int)sizeof(__nv_bfloat16);  // 73728
    const int attn_smem = (2 * 64 * SQ_STRIDE + 64 * 64) * (int)sizeof(float);
    cudaFuncSetAttribute(gemm_mma_bf16x3, cudaFuncAttributeMaxDynamicSharedMemorySize, gemm_smem);
    cudaFuncSetAttribute(attn_kernel, cudaFuncAttributeMaxDynamicSharedMemorySize, attn_smem);

    dim3 tgrid(CH / 32, CH / 32), tblk(32, 8);
    transpose_split_kernel<<<tgrid, tblk>>>(Wq, wthi + 0 * CH * CH, wtlo + 0 * CH * CH);
    transpose_split_kernel<<<tgrid, tblk>>>(Wk, wthi + 1 * CH * CH, wtlo + 1 * CH * CH);
    transpose_split_kernel<<<tgrid, tblk>>>(Wv, wthi + 2 * CH * CH, wtlo + 2 * CH * CH);
    transpose_split_kernel<<<tgrid, tblk>>>(Wp, wthi + 3 * CH * CH, wtlo + 3 * CH * CH);

    split_kernel<<<MROWS * CH / (256 * 4), 256>>>(x, xhi, xlo, MROWS * CH / 4);

    dim3 ggrid(CH / 128, MROWS / 128);  // (8, 32)
    gemm_mma_bf16x3<<<ggrid, 256, gemm_smem>>>(xhi, xlo, wthi + 0 * CH * CH, wtlo + 0 * CH * CH, bq, q, CH, CH);
    gemm_mma_bf16x3<<<ggrid, 256, gemm_smem>>>(xhi, xlo, wthi + 1 * CH * CH, wtlo + 1 * CH * CH, bk, k, CH, CH);
    gemm_mma_bf16x3<<<ggrid, 256, gemm_smem>>>(xhi, xlo, wthi + 2 * CH * CH, wtlo + 2 * CH * CH, bv, v, CH, CH);

    attn_kernel<<<dim3(SEQ / 64, BATCH * NHEAD), 256, attn_smem>>>(q, k, v, att);

    split_kernel<<<MROWS * CH / (256 * 4), 256>>>(att, xhi, xlo, MROWS * CH / 4);
    gemm_mma_bf16x3<<<ggrid, 256, gemm_smem>>>(xhi, xlo, wthi + 3 * CH * CH, wtlo + 3 * CH * CH, bp, out, CH, CH);
}

// round 5
// speedup vs baseline: 2.4451x; 1.6776x over previous
#include <cuda_runtime.h>
#include <cuda_bf16.h>
#include <math.h>
#include <stdint.h>

#define BATCH 2
#define SEQ   2048
#define CH    1024
#define NHEAD 16
#define HD    64
#define MROWS (BATCH*SEQ)   // 4096

// ---------------------------------------------------------------------------
// scratch (allocation is forbidden; device globals are the sanctioned path)
// all intermediates live as bf16 hi/lo pairs
// ---------------------------------------------------------------------------
__device__ __nv_bfloat16 g_xhi[MROWS*CH];      // split of x; reused for att split
__device__ __nv_bfloat16 g_xlo[MROWS*CH];
__device__ __nv_bfloat16 g_qhi[MROWS*CH];
__device__ __nv_bfloat16 g_qlo[MROWS*CH];
__device__ __nv_bfloat16 g_khi[MROWS*CH];
__device__ __nv_bfloat16 g_klo[MROWS*CH];
__device__ __nv_bfloat16 g_vhi[MROWS*CH];
__device__ __nv_bfloat16 g_vlo[MROWS*CH];
__device__ __nv_bfloat16 g_wthi[4*CH*CH];      // W^T hi, 4 weights
__device__ __nv_bfloat16 g_wtlo[4*CH*CH];      // W^T lo

// ---------------------------------------------------------------------------
// helpers
// ---------------------------------------------------------------------------
__device__ __forceinline__ void mma16816(float c[4],
                                         uint32_t a0, uint32_t a1,
                                         uint32_t a2, uint32_t a3,
                                         uint32_t b0, uint32_t b1)
{
    asm volatile(
        "mma.sync.aligned.m16n8k16.row.col.f32.bf16.bf16.f32 "
        "{%0,%1,%2,%3}, {%4,%5,%6,%7}, {%8,%9}, {%0,%1,%2,%3};"
        : "+f"(c[0]), "+f"(c[1]), "+f"(c[2]), "+f"(c[3])
        : "r"(a0), "r"(a1), "r"(a2), "r"(a3), "r"(b0), "r"(b1));
}

__device__ __forceinline__ void split2(float x, float y, uint32_t& hi, uint32_t& lo)
{
    __nv_bfloat16 hx = __float2bfloat16(x);
    __nv_bfloat16 hy = __float2bfloat16(y);
    __nv_bfloat16 lx = __float2bfloat16(x - __bfloat162float(hx));
    __nv_bfloat16 ly = __float2bfloat16(y - __bfloat162float(hy));
    __nv_bfloat162 hv(hx, hy), lv(lx, ly);
    hi = *(uint32_t*)&hv;
    lo = *(uint32_t*)&lv;
}

// ---------------------------------------------------------------------------
// fp32 -> bf16 hi/lo elementwise split (vectorized by 4)
// ---------------------------------------------------------------------------
__global__ void split_kernel(const float* __restrict__ x,
                             __nv_bfloat16* __restrict__ hi,
                             __nv_bfloat16* __restrict__ lo, int n4)
{
    int i = blockIdx.x * blockDim.x + threadIdx.x;
    if (i >= n4) return;
    float4 v = ((const float4*)x)[i];
    float f[4] = {v.x, v.y, v.z, v.w};
    __nv_bfloat16 h[4], l[4];
#pragma unroll
    for (int u = 0; u < 4; u++) {
        h[u] = __float2bfloat16(f[u]);
        l[u] = __float2bfloat16(f[u] - __bfloat162float(h[u]));
    }
    ((uint2*)hi)[i] = *(uint2*)h;
    ((uint2*)lo)[i] = *(uint2*)l;
}

// ---------------------------------------------------------------------------
// W [K,N] fp32 -> W^T [N,K] bf16 hi/lo   (32x32 tiles, block 32x8)
// ---------------------------------------------------------------------------
__global__ void transpose_split_kernel(const float* __restrict__ W,
                                       __nv_bfloat16* __restrict__ Thi,
                                       __nv_bfloat16* __restrict__ Tlo)
{
    __shared__ float t[32][33];
    const int kk = blockIdx.y * 32;
    const int nn = blockIdx.x * 32;
    const int tx = threadIdx.x, ty = threadIdx.y;
#pragma unroll
    for (int j = 0; j < 4; j++)
        t[ty + j * 8][tx] = W[(size_t)(kk + ty + j * 8) * CH + nn + tx];
    __syncthreads();
#pragma unroll
    for (int j = 0; j < 4; j++) {
        float v = t[tx][ty + j * 8];
        __nv_bfloat16 h = __float2bfloat16(v);
        __nv_bfloat16 l = __float2bfloat16(v - __bfloat162float(h));
        size_t o = (size_t)(nn + ty + j * 8) * CH + kk + tx;
        Thi[o] = h;
        Tlo[o] = l;
    }
}

// ---------------------------------------------------------------------------
// out = (Ahi+Alo)[M,K] @ (Bhi+Blo)[N,K]^T + bias  (bf16x3 on HMMA)
// CTA 128x128, 8 warps (2x4), warp tile 64x32, K-chunk 64.
// If outf != null -> fp32 out; else bf16 hi/lo split out.
// ---------------------------------------------------------------------------
#define PITCH 72

__global__ void __launch_bounds__(256, 2)
gemm_mma_bf16x3(const __nv_bfloat16* __restrict__ Ahi,
                const __nv_bfloat16* __restrict__ Alo,
                const __nv_bfloat16* __restrict__ Bhi,   // [N,K] = W^T
                const __nv_bfloat16* __restrict__ Blo,
                const float* __restrict__ bias,
                float* __restrict__ outf,
                __nv_bfloat16* __restrict__ outhi,
                __nv_bfloat16* __restrict__ outlo,
                int K, int N)
{
    extern __shared__ __nv_bfloat16 sm[];
    __nv_bfloat16* sAh = sm;
    __nv_bfloat16* sAl = sm + 128 * PITCH;
    __nv_bfloat16* sBh = sm + 2 * 128 * PITCH;
    __nv_bfloat16* sBl = sm + 3 * 128 * PITCH;

    const int tid  = threadIdx.x;
    const int warp = tid >> 5;
    const int lane = tid & 31;
    const int grp  = lane >> 2;
    const int tig  = lane & 3;
    const int wm   = warp >> 2;
    const int wn   = warp & 3;

    const int m0 = blockIdx.y * 128;
    const int n0 = blockIdx.x * 128;

    float c[4][4][4];
#pragma unroll
    for (int mt = 0; mt < 4; mt++)
#pragma unroll
        for (int nt = 0; nt < 4; nt++)
#pragma unroll
            for (int f = 0; f < 4; f++) c[mt][nt][f] = 0.f;

    const int row = tid >> 3;
    const int cg  = tid & 7;

    for (int k0 = 0; k0 < K; k0 += 64) {
        __syncthreads();
#pragma unroll
        for (int i = 0; i < 4; i++) {
            int r = row + i * 32;
            size_t ga = (size_t)(m0 + r) * K + k0 + cg * 8;
            size_t gb = (size_t)(n0 + r) * K + k0 + cg * 8;
            int so = r * PITCH + cg * 8;
            *(uint4*)&sAh[so] = *(const uint4*)(Ahi + ga);
            *(uint4*)&sAl[so] = *(const uint4*)(Alo + ga);
            *(uint4*)&sBh[so] = *(const uint4*)(Bhi + gb);
            *(uint4*)&sBl[so] = *(const uint4*)(Blo + gb);
        }
        __syncthreads();

#pragma unroll
        for (int ks = 0; ks < 4; ks++) {
            const int kof = ks * 16 + 2 * tig;
            uint32_t bh[4][2], bl[4][2];
#pragma unroll
            for (int nt = 0; nt < 4; nt++) {
                int nrow = wn * 32 + nt * 8 + grp;
                bh[nt][0] = *(const uint32_t*)&sBh[nrow * PITCH + kof];
                bh[nt][1] = *(const uint32_t*)&sBh[nrow * PITCH + kof + 8];
                bl[nt][0] = *(const uint32_t*)&sBl[nrow * PITCH + kof];
                bl[nt][1] = *(const uint32_t*)&sBl[nrow * PITCH + kof + 8];
            }
#pragma unroll
            for (int mt = 0; mt < 4; mt++) {
                int mrow = wm * 64 + mt * 16 + grp;
                uint32_t ah0 = *(const uint32_t*)&sAh[mrow * PITCH + kof];
                uint32_t ah1 = *(const uint32_t*)&sAh[(mrow + 8) * PITCH + kof];
                uint32_t ah2 = *(const uint32_t*)&sAh[mrow * PITCH + kof + 8];
                uint32_t ah3 = *(const uint32_t*)&sAh[(mrow + 8) * PITCH + kof + 8];
                uint32_t al0 = *(const uint32_t*)&sAl[mrow * PITCH + kof];
                uint32_t al1 = *(const uint32_t*)&sAl[(mrow + 8) * PITCH + kof];
                uint32_t al2 = *(const uint32_t*)&sAl[mrow * PITCH + kof + 8];
                uint32_t al3 = *(const uint32_t*)&sAl[(mrow + 8) * PITCH + kof + 8];
#pragma unroll
                for (int nt = 0; nt < 4; nt++) {
                    mma16816(c[mt][nt], ah0, ah1, ah2, ah3, bh[nt][0], bh[nt][1]);
                    mma16816(c[mt][nt], ah0, ah1, ah2, ah3, bl[nt][0], bl[nt][1]);
                    mma16816(c[mt][nt], al0, al1, al2, al3, bh[nt][0], bh[nt][1]);
                }
            }
        }
    }

#pragma unroll
    for (int mt = 0; mt < 4; mt++) {
        int r0 = m0 + wm * 64 + mt * 16 + grp;
#pragma unroll
        for (int nt = 0; nt < 4; nt++) {
            int col = n0 + wn * 32 + nt * 8 + 2 * tig;
            float2 bv = *(const float2*)(bias + col);
            float v00 = c[mt][nt][0] + bv.x, v01 = c[mt][nt][1] + bv.y;
            float v10 = c[mt][nt][2] + bv.x, v11 = c[mt][nt][3] + bv.y;
            if (outf) {
                *(float2*)(outf + (size_t)r0 * N + col) = make_float2(v00, v01);
                *(float2*)(outf + (size_t)(r0 + 8) * N + col) = make_float2(v10, v11);
            } else {
                uint32_t h0, l0, h1, l1;
                split2(v00, v01, h0, l0);
                split2(v10, v11, h1, l1);
                *(uint32_t*)(outhi + (size_t)r0 * N + col) = h0;
                *(uint32_t*)(outlo + (size_t)r0 * N + col) = l0;
                *(uint32_t*)(outhi + (size_t)(r0 + 8) * N + col) = h1;
                *(uint32_t*)(outlo + (size_t)(r0 + 8) * N + col) = l1;
            }
        }
    }
}

// ---------------------------------------------------------------------------
// HMMA flash attention, swapped roles:
//   out[i] = sum_{j<=i} softmax_j( (k_i . q_j)/8 ) * v_j
// Q-role := k rows, K-role := q rows. Br=Bc=64, 4 warps, warp = 16 i-rows.
// bf16x3 split on S and PV. P never touches smem (C-frag == A-frag layout).
// Output: bf16 hi/lo split of att (consumed by final GEMM).
// ---------------------------------------------------------------------------
#define AP 72

__global__ void __launch_bounds__(128, 3)
attn_mma(const __nv_bfloat16* __restrict__ qhi, const __nv_bfloat16* __restrict__ qlo,
         const __nv_bfloat16* __restrict__ khi, const __nv_bfloat16* __restrict__ klo,
         const __nv_bfloat16* __restrict__ vhi, const __nv_bfloat16* __restrict__ vlo,
         __nv_bfloat16* __restrict__ ohi, __nv_bfloat16* __restrict__ olo)
{
    extern __shared__ __nv_bfloat16 sa[];
    __nv_bfloat16* sQh = sa;                    // [64][AP] rows i (k-buffer)
    __nv_bfloat16* sQl = sa + 64 * AP;
    __nv_bfloat16* sKh = sa + 2 * 64 * AP;      // [64][AP] rows j (q-buffer)
    __nv_bfloat16* sKl = sa + 3 * 64 * AP;
    __nv_bfloat16* sVh = sa + 4 * 64 * AP;      // [64][AP] transposed: [d][j]
    __nv_bfloat16* sVl = sa + 5 * 64 * AP;

    const int tid  = threadIdx.x;
    const int warp = tid >> 5;
    const int lane = tid & 31;
    const int g    = lane >> 2;
    const int tig  = lane & 3;

    const int i0 = blockIdx.x * 64;
    const int bh = blockIdx.y;
    const int b  = bh >> 4;
    const int h  = bh & 15;
    const size_t base = (size_t)b * SEQ * CH + (size_t)h * HD;

    // load Q tile (k-buffer rows i0..i0+63) once
    {
        int r = tid >> 3, cg = tid & 7;
#pragma unroll
        for (int i = 0; i < 4; i++) {
            int rr = r + i * 16;
            size_t go = base + (size_t)(i0 + rr) * CH + cg * 8;
            *(uint4*)&sQh[rr * AP + cg * 8] = *(const uint4*)(khi + go);
            *(uint4*)&sQl[rr * AP + cg * 8] = *(const uint4*)(klo + go);
        }
    }

    float acc[8][4];
#pragma unroll
    for (int nd = 0; nd < 8; nd++)
#pragma unroll
        for (int f = 0; f < 4; f++) acc[nd][f] = 0.f;
    float m0r = -INFINITY, m1r = -INFINITY, l0r = 0.f, l1r = 0.f;

    const float scl = 0.125f * 1.44269504f;  // 1/sqrt(64) * log2(e)
    const int ig0 = i0 + warp * 16 + g;
    const int ig1 = ig0 + 8;
    const int ar  = warp * 16 + g;

    for (int j0 = 0; j0 <= i0; j0 += 64) {
        __syncthreads();
        // load K tile (q-buffer rows j0..j0+63)
        {
            int r = tid >> 3, cg = tid & 7;
#pragma unroll
            for (int i = 0; i < 4; i++) {
                int rr = r + i * 16;
                size_t go = base + (size_t)(j0 + rr) * CH + cg * 8;
                *(uint4*)&sKh[rr * AP + cg * 8] = *(const uint4*)(qhi + go);
                *(uint4*)&sKl[rr * AP + cg * 8] = *(const uint4*)(qlo + go);
            }
        }
        // load V tile transposed: sV[d][j]
        {
            int j = tid & 63, dh = tid >> 6;  // dh: 0..1
#pragma unroll
            for (int u = 0; u < 4; u++) {
                int d0 = dh * 32 + u * 8;
                size_t go = base + (size_t)(j0 + j) * CH + d0;
                uint4 th = *(const uint4*)(vhi + go);
                uint4 tl = *(const uint4*)(vlo + go);
                const __nv_bfloat16* ph = (const __nv_bfloat16*)&th;
                const __nv_bfloat16* pl = (const __nv_bfloat16*)&tl;
#pragma unroll
                for (int e = 0; e < 8; e++) {
                    sVh[(d0 + e) * AP + j] = ph[e];
                    sVl[(d0 + e) * AP + j] = pl[e];
                }
            }
        }
        __syncthreads();

        // ----- S = Q . K^T  (bf16x3) -----
        float sf[8][4];
#pragma unroll
        for (int nt = 0; nt < 8; nt++)
#pragma unroll
            for (int f = 0; f < 4; f++) sf[nt][f] = 0.f;

#pragma unroll
        for (int kd = 0; kd < 4; kd++) {
            const int kof = kd * 16 + 2 * tig;
            uint32_t ah0 = *(const uint32_t*)&sQh[ar * AP + kof];
            uint32_t ah1 = *(const uint32_t*)&sQh[(ar + 8) * AP + kof];
            uint32_t ah2 = *(const uint32_t*)&sQh[ar * AP + kof + 8];
            uint32_t ah3 = *(const uint32_t*)&sQh[(ar + 8) * AP + kof + 8];
            uint32_t al0 = *(const uint32_t*)&sQl[ar * AP + kof];
            uint32_t al1 = *(const uint32_t*)&sQl[(ar + 8) * AP + kof];
            uint32_t al2 = *(const uint32_t*)&sQl[ar * AP + kof + 8];
            uint32_t al3 = *(const uint32_t*)&sQl[(ar + 8) * AP + kof + 8];
#pragma unroll
            for (int nt = 0; nt < 8; nt++) {
                int nr = nt * 8 + g;
                uint32_t bh0 = *(const uint32_t*)&sKh[nr * AP + kof];
                uint32_t bh1 = *(const uint32_t*)&sKh[nr * AP + kof + 8];
                uint32_t bl0 = *(const uint32_t*)&sKl[nr * AP + kof];
                uint32_t bl1 = *(const uint32_t*)&sKl[nr * AP + kof + 8];
                mma16816(sf[nt], ah0, ah1, ah2, ah3, bh0, bh1);
                mma16816(sf[nt], ah0, ah1, ah2, ah3, bl0, bl1);
                mma16816(sf[nt], al0, al1, al2, al3, bh0, bh1);
            }
        }

        // scale (log2 domain) + causal mask on diagonal tile
        if (j0 == i0) {
#pragma unroll
            for (int nt = 0; nt < 8; nt++)
#pragma unroll
                for (int cc = 0; cc < 2; cc++) {
                    int jg = j0 + nt * 8 + 2 * tig + cc;
                    sf[nt][cc]     = (jg <= ig0) ? sf[nt][cc] * scl     : -INFINITY;
                    sf[nt][2 + cc] = (jg <= ig1) ? sf[nt][2 + cc] * scl : -INFINITY;
                }
        } else {
#pragma unroll
            for (int nt = 0; nt < 8; nt++)
#pragma unroll
                for (int f = 0; f < 4; f++) sf[nt][f] *= scl;
        }

        // ----- online softmax (rows g and g+8 of this warp's 16) -----
        float mx0 = -INFINITY, mx1 = -INFINITY;
#pragma unroll
        for (int nt = 0; nt < 8; nt++) {
            mx0 = fmaxf(mx0, fmaxf(sf[nt][0], sf[nt][1]));
            mx1 = fmaxf(mx1, fmaxf(sf[nt][2], sf[nt][3]));
        }
        mx0 = fmaxf(mx0, __shfl_xor_sync(0xffffffffu, mx0, 1));
        mx0 = fmaxf(mx0, __shfl_xor_sync(0xffffffffu, mx0, 2));
        mx1 = fmaxf(mx1, __shfl_xor_sync(0xffffffffu, mx1, 1));
        mx1 = fmaxf(mx1, __shfl_xor_sync(0xffffffffu, mx1, 2));

        float mn0 = fmaxf(m0r, mx0), mn1 = fmaxf(m1r, mx1);
        float a0f = exp2f(m0r - mn0), a1f = exp2f(m1r - mn1);
        m0r = mn0; m1r = mn1;

        float ps0 = 0.f, ps1 = 0.f;
#pragma unroll
        for (int nt = 0; nt < 8; nt++) {
            sf[nt][0] = exp2f(sf[nt][0] - mn0);
            sf[nt][1] = exp2f(sf[nt][1] - mn0);
            sf[nt][2] = exp2f(sf[nt][2] - mn1);
            sf[nt][3] = exp2f(sf[nt][3] - mn1);
            ps0 += sf[nt][0] + sf[nt][1];
            ps1 += sf[nt][2] + sf[nt][3];
        }
        ps0 += __shfl_xor_sync(0xffffffffu, ps0, 1);
        ps0 += __shfl_xor_sync(0xffffffffu, ps0, 2);
        ps1 += __shfl_xor_sync(0xffffffffu, ps1, 1);
        ps1 += __shfl_xor_sync(0xffffffffu, ps1, 2);
        l0r = l0r * a0f + ps0;
        l1r = l1r * a1f + ps1;

#pragma unroll
        for (int nd = 0; nd < 8; nd++) {
            acc[nd][0] *= a0f; acc[nd][1] *= a0f;
            acc[nd][2] *= a1f; acc[nd][3] *= a1f;
        }

        // ----- acc += P @ V  (P C-frag -> A-frag in registers, bf16x3) -----
#pragma unroll
        for (int ks = 0; ks < 4; ks++) {
            uint32_t ph0, pl0, ph1, pl1, ph2, pl2, ph3, pl3;
            split2(sf[2 * ks][0],     sf[2 * ks][1],     ph0, pl0);
            split2(sf[2 * ks][2],     sf[2 * ks][3],     ph1, pl1);
            split2(sf[2 * ks + 1][0], sf[2 * ks + 1][1], ph2, pl2);
            split2(sf[2 * ks + 1][2], sf[2 * ks + 1][3], ph3, pl3);
            const int kof = ks * 16 + 2 * tig;
#pragma unroll
            for (int nd = 0; nd < 8; nd++) {
                int nr = nd * 8 + g;
                uint32_t bh0 = *(const uint32_t*)&sVh[nr * AP + kof];
                uint32_t bh1 = *(const uint32_t*)&sVh[nr * AP + kof + 8];
                uint32_t bl0 = *(const uint32_t*)&sVl[nr * AP + kof];
                uint32_t bl1 = *(const uint32_t*)&sVl[nr * AP + kof + 8];
                mma16816(acc[nd], ph0, ph1, ph2, ph3, bh0, bh1);
                mma16816(acc[nd], ph0, ph1, ph2, ph3, bl0, bl1);
                mma16816(acc[nd], pl0, pl1, pl2, pl3, bh0, bh1);
            }
        }
    }

    // ----- epilogue: normalize, split to bf16 hi/lo, store -----
    const float inv0 = 1.f / l0r, inv1 = 1.f / l1r;
    const size_t r0o = base + (size_t)ig0 * CH;
    const size_t r1o = base + (size_t)ig1 * CH;
#pragma unroll
    for (int nd = 0; nd < 8; nd++) {
        int col = nd * 8 + 2 * tig;
        uint32_t h0, l0, h1, l1;
        split2(acc[nd][0] * inv0, acc[nd][1] * inv0, h0, l0);
        split2(acc[nd][2] * inv1, acc[nd][3] * inv1, h1, l1);
        *(uint32_t*)(ohi + r0o + col) = h0;
        *(uint32_t*)(olo + r0o + col) = l0;
        *(uint32_t*)(ohi + r1o + col) = h1;
        *(uint32_t*)(olo + r1o + col) = l1;
    }
}

// ---------------------------------------------------------------------------
extern "C" void kernel_launch(void* const* d_in, const int* in_sizes, int n_in,
                              void* d_out, int out_size)
{
    const float* x  = (const float*)d_in[0];
    const float* Wq = (const float*)d_in[1];
    const float* bq = (const float*)d_in[2];
    const float* Wk = (const float*)d_in[3];
    const float* bk = (const float*)d_in[4];
    const float* Wv = (const float*)d_in[5];
    const float* bv = (const float*)d_in[6];
    const float* Wp = (const float*)d_in[7];
    const float* bp = (const float*)d_in[8];
    float* out = (float*)d_out;

    __nv_bfloat16 *xhi, *xlo, *qhi, *qlo, *khi, *klo, *vhi, *vlo, *wthi, *wtlo;
    cudaGetSymbolAddress((void**)&xhi,  g_xhi);
    cudaGetSymbolAddress((void**)&xlo,  g_xlo);
    cudaGetSymbolAddress((void**)&qhi,  g_qhi);
    cudaGetSymbolAddress((void**)&qlo,  g_qlo);
    cudaGetSymbolAddress((void**)&khi,  g_khi);
    cudaGetSymbolAddress((void**)&klo,  g_klo);
    cudaGetSymbolAddress((void**)&vhi,  g_vhi);
    cudaGetSymbolAddress((void**)&vlo,  g_vlo);
    cudaGetSymbolAddress((void**)&wthi, g_wthi);
    cudaGetSymbolAddress((void**)&wtlo, g_wtlo);

    const int gemm_smem = 4 * 128 * PITCH * (int)sizeof(__nv_bfloat16);  // 73728
    const int attn_smem = 6 * 64 * AP * (int)sizeof(__nv_bfloat16);      // 55296
    cudaFuncSetAttribute(gemm_mma_bf16x3, cudaFuncAttributeMaxDynamicSharedMemorySize, gemm_smem);
    cudaFuncSetAttribute(attn_mma, cudaFuncAttributeMaxDynamicSharedMemorySize, attn_smem);

    dim3 tgrid(CH / 32, CH / 32), tblk(32, 8);
    transpose_split_kernel<<<tgrid, tblk>>>(Wq, wthi + 0 * CH * CH, wtlo + 0 * CH * CH);
    transpose_split_kernel<<<tgrid, tblk>>>(Wk, wthi + 1 * CH * CH, wtlo + 1 * CH * CH);
    transpose_split_kernel<<<tgrid, tblk>>>(Wv, wthi + 2 * CH * CH, wtlo + 2 * CH * CH);
    transpose_split_kernel<<<tgrid, tblk>>>(Wp, wthi + 3 * CH * CH, wtlo + 3 * CH * CH);

    split_kernel<<<MROWS * CH / (256 * 4), 256>>>(x, xhi, xlo, MROWS * CH / 4);

    dim3 ggrid(CH / 128, MROWS / 128);  // (8, 32)
    gemm_mma_bf16x3<<<ggrid, 256, gemm_smem>>>(xhi, xlo, wthi + 0 * CH * CH, wtlo + 0 * CH * CH,
                                               bq, nullptr, qhi, qlo, CH, CH);
    gemm_mma_bf16x3<<<ggrid, 256, gemm_smem>>>(xhi, xlo, wthi + 1 * CH * CH, wtlo + 1 * CH * CH,
                                               bk, nullptr, khi, klo, CH, CH);
    gemm_mma_bf16x3<<<ggrid, 256, gemm_smem>>>(xhi, xlo, wthi + 2 * CH * CH, wtlo + 2 * CH * CH,
                                               bv, nullptr, vhi, vlo, CH, CH);

    // attention writes its hi/lo split into xhi/xlo (x split no longer needed)
    attn_mma<<<dim3(SEQ / 64, BATCH * NHEAD), 128, attn_smem>>>(qhi, qlo, khi, klo, vhi, vlo,
                                                                xhi, xlo);

    gemm_mma_bf16x3<<<ggrid, 256, gemm_smem>>>(xhi, xlo, wthi + 3 * CH * CH, wtlo + 3 * CH * CH,
                                               bp, out, nullptr, nullptr, CH, CH);
}